// round 4
// baseline (speedup 1.0000x reference)
#include <cuda_runtime.h>
#include <math.h>

#define NROWS 131072   // B*T*NN = 128*128*8
#define EMAX  1048576
typedef unsigned long long ull;

__device__ float g_dinv[NROWS];
__device__ int   g_cnt[NROWS];
__device__ int   g_rowptr[NROWS + 1];
__device__ int   g_cursor[NROWS];
__device__ int   g_bsum[256];
__device__ int   g_bpre[256];
__device__ float2 g_edge[EMAX];
__device__ float g_bufA[NROWS * 64];
__device__ float g_bufB[NROWS * 64];
__device__ float g_bufC[NROWS * 64];
__device__ float g_stats[128];   // [0:64) sum, [64:128) sumsq
__device__ float g_scale[64];
__device__ float g_shift[64];
__device__ float g_wsum[72];

// ---------------------------------------------------------------- f32x2 helpers
__device__ __forceinline__ void fma2(ull& d, ull a, ull b) {
    asm("fma.rn.f32x2 %0, %1, %2, %0;" : "+l"(d) : "l"(a), "l"(b));
}
__device__ __forceinline__ ull packf(float x, float y) {
    ull r; asm("mov.b64 %0, {%1, %2};" : "=l"(r) : "f"(x), "f"(y)); return r;
}
__device__ __forceinline__ float f_lo(ull v) { return __int_as_float((int)(unsigned)(v & 0xffffffffull)); }
__device__ __forceinline__ float f_hi(ull v) { return __int_as_float((int)(unsigned)(v >> 32)); }

// ---------------------------------------------------------------- CSR build
__global__ void k_zero_cnt() {
    int i = blockIdx.x * 256 + threadIdx.x;
    if (i < NROWS) g_cnt[i] = 0;
}
__global__ void k_hist(const int* __restrict__ dst, int E) {
    int e = blockIdx.x * 256 + threadIdx.x;
    if (e < E) atomicAdd(&g_cnt[dst[e]], 1);
}
__global__ void k_scan1() {
    __shared__ int ws[4];
    int b = blockIdx.x, t = threadIdx.x;
    int4 v = reinterpret_cast<const int4*>(g_cnt)[b * 128 + t];
    int s0 = v.x, s1 = s0 + v.y, s2 = s1 + v.z, s3 = s2 + v.w;
    int lane = t & 31, warp = t >> 5;
    int x = s3;
    #pragma unroll
    for (int o = 1; o < 32; o <<= 1) {
        int y = __shfl_up_sync(~0u, x, o);
        if (lane >= o) x += y;
    }
    if (lane == 31) ws[warp] = x;
    __syncthreads();
    int woff = 0;
    #pragma unroll
    for (int i = 0; i < 4; i++) if (i < warp) woff += ws[i];
    int excl = woff + x - s3;
    int4 o4 = make_int4(excl, excl + s0, excl + s1, excl + s2);
    reinterpret_cast<int4*>(g_rowptr)[b * 128 + t] = o4;
    if (t == 127) g_bsum[b] = woff + x;
}
__global__ void k_scan2() {
    __shared__ int ws[8];
    int t = threadIdx.x;
    int v = g_bsum[t];
    int lane = t & 31, warp = t >> 5;
    int x = v;
    #pragma unroll
    for (int o = 1; o < 32; o <<= 1) {
        int y = __shfl_up_sync(~0u, x, o);
        if (lane >= o) x += y;
    }
    if (lane == 31) ws[warp] = x;
    __syncthreads();
    int woff = 0;
    #pragma unroll
    for (int i = 0; i < 8; i++) if (i < warp) woff += ws[i];
    g_bpre[t] = woff + x - v;
}
__global__ void k_scan3(int E) {
    int i = blockIdx.x * 256 + threadIdx.x;
    if (i >= NROWS) return;
    int r = g_rowptr[i] + g_bpre[i >> 9];
    g_rowptr[i] = r;
    g_cursor[i] = r;
    g_dinv[i] = rsqrtf((float)(g_cnt[i] + 1));
    if (i == 0) g_rowptr[NROWS] = E;
}
__global__ void k_place(const int* __restrict__ src, const int* __restrict__ dst, int E) {
    int e = blockIdx.x * 256 + threadIdx.x;
    if (e >= E) return;
    int s = src[e], d = dst[e];
    int pos = atomicAdd(&g_cursor[d], 1);
    g_edge[pos] = make_float2(__int_as_float(s), g_dinv[s] * g_dinv[d]);
}

// ------------------------------------------------- gather aggregation (warp/row)
__global__ void k_gather32(const float* __restrict__ X, float* __restrict__ Y) {
    if (blockIdx.x == 0 && threadIdx.x < 128) g_stats[threadIdx.x] = 0.0f;
    int d = blockIdx.x * 8 + (threadIdx.x >> 5);
    int lane = threadIdx.x & 31;
    float dv = g_dinv[d];
    float a = X[(size_t)d * 32 + lane] * dv * dv;
    int p1 = g_rowptr[d + 1];
    for (int p = g_rowptr[d]; p < p1; ++p) {
        float2 ec = g_edge[p];
        int s = __float_as_int(ec.x);
        a = fmaf(ec.y, X[(size_t)s * 32 + lane], a);
    }
    Y[(size_t)d * 32 + lane] = a;
}
__global__ void k_gather64(const float* __restrict__ X, float* __restrict__ Y) {
    if (blockIdx.x == 0 && threadIdx.x < 128) g_stats[threadIdx.x] = 0.0f;
    int d = blockIdx.x * 8 + (threadIdx.x >> 5);
    int lane = threadIdx.x & 31;
    float dv = g_dinv[d];
    float sc = dv * dv;
    const float2* X2 = reinterpret_cast<const float2*>(X);
    float2 a = X2[(size_t)d * 32 + lane];
    a.x *= sc; a.y *= sc;
    int p1 = g_rowptr[d + 1];
    for (int p = g_rowptr[d]; p < p1; ++p) {
        float2 ec = g_edge[p];
        int s = __float_as_int(ec.x);
        float2 v = X2[(size_t)s * 32 + lane];
        a.x = fmaf(ec.y, v.x, a.x);
        a.y = fmaf(ec.y, v.y, a.y);
    }
    reinterpret_cast<float2*>(Y)[(size_t)d * 32 + lane] = a;
}

// ---------------------------------------------------------------- unified GEMM (FFMA2)
template<int K, int TAPS, int AMODE, int WLAYOUT, int EMODE>
__global__ void __launch_bounds__(256)
k_gemm(const float* __restrict__ A, const float* __restrict__ W,
       const float* __restrict__ bias, float* __restrict__ out) {
    constexpr int P = (TAPS == 3) ? 146 : 130;
    constexpr int ROWS_T = (TAPS == 3) ? 144 : 128;
    constexpr int CH = K / 4;
    extern __shared__ float smem[];
    float* Asm  = smem;             // K * P floats
    float* Wdup = smem + K * P;     // K * 128 floats
    const int tid = threadIdx.x;
    const int cg = tid & 15, rg = tid >> 4;
    const int c0 = cg * 4, r0 = rg * 8;
    const int row0 = blockIdx.x << 7;

    ull acc[4][4];
    {
        float4 bb = reinterpret_cast<const float4*>(bias)[cg];
        ull b0 = packf(bb.x, bb.x), b1 = packf(bb.y, bb.y);
        ull b2 = packf(bb.z, bb.z), b3 = packf(bb.w, bb.w);
        #pragma unroll
        for (int p = 0; p < 4; p++) { acc[p][0] = b0; acc[p][1] = b1; acc[p][2] = b2; acc[p][3] = b3; }
    }

    #pragma unroll
    for (int idx = tid; idx < ROWS_T * CH; idx += 256) {
        int rr = idx / CH, kc = idx - rr * CH;
        float4 v;
        if (TAPS == 3) {
            int lb = (row0 & 1023) + rr - 8;
            if ((unsigned)lb < 1024u)
                v = reinterpret_cast<const float4*>(A)[(size_t)(row0 + rr - 8) * CH + kc];
            else
                v = make_float4(0.f, 0.f, 0.f, 0.f);
        } else {
            v = reinterpret_cast<const float4*>(A)[(size_t)(row0 + rr) * CH + kc];
        }
        if (AMODE == 1) {
            int k4 = kc * 4;
            v.x = fmaxf(0.f, fmaf(v.x, g_scale[k4 + 0], g_shift[k4 + 0]));
            v.y = fmaxf(0.f, fmaf(v.y, g_scale[k4 + 1], g_shift[k4 + 1]));
            v.z = fmaxf(0.f, fmaf(v.z, g_scale[k4 + 2], g_shift[k4 + 2]));
            v.w = fmaxf(0.f, fmaf(v.w, g_scale[k4 + 3], g_shift[k4 + 3]));
        }
        int base = (kc * 4) * P + rr;
        Asm[base] = v.x; Asm[base + P] = v.y; Asm[base + 2 * P] = v.z; Asm[base + 3 * P] = v.w;
    }

    #pragma unroll
    for (int tap = 0; tap < TAPS; ++tap) {
        __syncthreads();
        #pragma unroll
        for (int idx = tid; idx < K * 64; idx += 256) {
            int k = idx >> 6, c = idx & 63;
            float w;
            if (WLAYOUT == 0)      w = W[k * 64 + c];
            else if (WLAYOUT == 1) w = W[c * 64 + k];
            else                   w = W[c * 192 + k * 3 + tap];
            int o = k * 128 + 2 * c;
            Wdup[o] = w; Wdup[o + 1] = w;
        }
        __syncthreads();
        const float* Abase = Asm + r0 + ((TAPS == 3) ? 8 * tap : 0);
        #pragma unroll 8
        for (int k = 0; k < K; k++) {
            const ull* Ap = reinterpret_cast<const ull*>(Abase + k * P);
            ull a0 = Ap[0], a1 = Ap[1], a2 = Ap[2], a3 = Ap[3];
            const ull* Wp = reinterpret_cast<const ull*>(Wdup + k * 128) + c0;
            ull w0 = Wp[0], w1 = Wp[1], w2 = Wp[2], w3 = Wp[3];
            fma2(acc[0][0], a0, w0); fma2(acc[0][1], a0, w1); fma2(acc[0][2], a0, w2); fma2(acc[0][3], a0, w3);
            fma2(acc[1][0], a1, w0); fma2(acc[1][1], a1, w1); fma2(acc[1][2], a1, w2); fma2(acc[1][3], a1, w3);
            fma2(acc[2][0], a2, w0); fma2(acc[2][1], a2, w1); fma2(acc[2][2], a2, w2); fma2(acc[2][3], a2, w3);
            fma2(acc[3][0], a3, w0); fma2(acc[3][1], a3, w1); fma2(acc[3][2], a3, w2); fma2(acc[3][3], a3, w3);
        }
    }

    if (EMODE == 0 || EMODE == 1) {
        #pragma unroll
        for (int p = 0; p < 4; p++) {
            int r = row0 + r0 + 2 * p;
            float4 lo4 = make_float4(f_lo(acc[p][0]), f_lo(acc[p][1]), f_lo(acc[p][2]), f_lo(acc[p][3]));
            float4 hi4 = make_float4(f_hi(acc[p][0]), f_hi(acc[p][1]), f_hi(acc[p][2]), f_hi(acc[p][3]));
            *reinterpret_cast<float4*>(out + (size_t)r * 64 + c0) = lo4;
            *reinterpret_cast<float4*>(out + (size_t)(r + 1) * 64 + c0) = hi4;
        }
    }
    if (EMODE == 1) {
        float* red = smem;
        __syncthreads();
        if (tid < 128) red[tid] = 0.f;
        __syncthreads();
        #pragma unroll
        for (int j = 0; j < 4; j++) {
            float s = 0.f, s2 = 0.f;
            #pragma unroll
            for (int p = 0; p < 4; p++) {
                float a = f_lo(acc[p][j]), b = f_hi(acc[p][j]);
                s += a + b; s2 += a * a + b * b;
            }
            atomicAdd(&red[c0 + j], s);
            atomicAdd(&red[64 + c0 + j], s2);
        }
        __syncthreads();
        if (tid < 128) atomicAdd(&g_stats[tid], red[tid]);
    }
    if (EMODE == 2) {
        #pragma unroll
        for (int p = 0; p < 4; p++) {
            #pragma unroll
            for (int half = 0; half < 2; half++) {
                int grow = row0 + r0 + 2 * p + half;
                int b = grow >> 10, t = (grow >> 3) & 127, nn = grow & 7;
                size_t base = ((((size_t)b * 64 + c0) * 8 + nn) << 7) + t;
                float v0 = half ? f_hi(acc[p][0]) : f_lo(acc[p][0]);
                float v1 = half ? f_hi(acc[p][1]) : f_lo(acc[p][1]);
                float v2 = half ? f_hi(acc[p][2]) : f_lo(acc[p][2]);
                float v3 = half ? f_hi(acc[p][3]) : f_lo(acc[p][3]);
                out[base       ] = tanhf(v0);
                out[base + 1024] = tanhf(v1);
                out[base + 2048] = tanhf(v2);
                out[base + 3072] = tanhf(v3);
            }
        }
    }
}

// ---------------------------------------------------------------- BN finalize
__global__ void k_bn_fin(const float* __restrict__ g, const float* __restrict__ b) {
    int c = threadIdx.x;
    if (c >= 64) return;
    const float inv = 1.0f / (float)NROWS;
    float mean = g_stats[c] * inv;
    float var  = g_stats[64 + c] * inv - mean * mean;
    float sc = rsqrtf(var + 1e-5f) * g[c];
    g_scale[c] = sc;
    g_shift[c] = b[c] - mean * sc;
}

// ------------------------------------------------- regression prep + final reduce
__global__ void k_prep_reg(const float* __restrict__ rw, const float* __restrict__ rb,
                           float* __restrict__ out) {
    int t = blockIdx.x * 256 + threadIdx.x;
    if (t < 1024) out[t] = 0.0f;
    if (t < 64) {
        float s = 0.f;
        #pragma unroll
        for (int k = 0; k < 8; k++) s += rw[t * 8 + k];
        g_wsum[t] = s;
    }
    if (t == 0) {
        float s = 0.f;
        #pragma unroll
        for (int k = 0; k < 8; k++) s += rb[k];
        g_wsum[64] = s;
    }
}
__global__ void k_reg(const float* __restrict__ X, float* __restrict__ out) {
    int r = blockIdx.x * 256 + threadIdx.x;
    if (r >= NROWS) return;
    const float4* xp = reinterpret_cast<const float4*>(X + (size_t)r * 64);
    float s = 0.f;
    #pragma unroll
    for (int q = 0; q < 16; q++) {
        float4 v = xp[q];
        s += v.x * g_wsum[q * 4 + 0] + v.y * g_wsum[q * 4 + 1]
           + v.z * g_wsum[q * 4 + 2] + v.w * g_wsum[q * 4 + 3];
    }
    float val = (s + g_wsum[64]) * (1.0f / 1024.0f);
    atomicAdd(&out[((r >> 10) << 3) + (r & 7)], val);
}

// ---------------------------------------------------------------- launch
extern "C" void kernel_launch(void* const* d_in, const int* in_sizes, int n_in,
                              void* d_out, int out_size) {
    const float* x      = (const float*)d_in[0];
    const int*   ei     = (const int*)  d_in[1];
    const float* gcn1_w = (const float*)d_in[2];
    const float* gcn1_b = (const float*)d_in[3];
    const float* t1_w   = (const float*)d_in[4];
    const float* t1_b   = (const float*)d_in[5];
    const float* bn1_g  = (const float*)d_in[6];
    const float* bn1_b  = (const float*)d_in[7];
    const float* o1_w   = (const float*)d_in[8];
    const float* o1_b   = (const float*)d_in[9];
    const float* gcn2_w = (const float*)d_in[10];
    const float* gcn2_b = (const float*)d_in[11];
    const float* t2_w   = (const float*)d_in[12];
    const float* t2_b   = (const float*)d_in[13];
    const float* bn2_g  = (const float*)d_in[14];
    const float* bn2_b  = (const float*)d_in[15];
    const float* o2_w   = (const float*)d_in[16];
    const float* o2_b   = (const float*)d_in[17];
    const float* reg_w  = (const float*)d_in[18];
    const float* reg_b  = (const float*)d_in[19];
    float* out = (float*)d_out;

    int E = in_sizes[1] / 2;
    const int* src = ei;
    const int* dst = ei + E;

    float *bufA, *bufB, *bufC;
    cudaGetSymbolAddress((void**)&bufA, g_bufA);
    cudaGetSymbolAddress((void**)&bufB, g_bufB);
    cudaGetSymbolAddress((void**)&bufC, g_bufC);

    const int sm32  = (32 * 130 + 32 * 128) * 4;
    const int sm64  = (64 * 130 + 64 * 128) * 4;
    const int sm64t = (64 * 146 + 64 * 128) * 4;
    cudaFuncSetAttribute(k_gemm<32, 1, 0, 0, 0>, cudaFuncAttributeMaxDynamicSharedMemorySize, sm32);
    cudaFuncSetAttribute(k_gemm<64, 3, 0, 2, 1>, cudaFuncAttributeMaxDynamicSharedMemorySize, sm64t);
    cudaFuncSetAttribute(k_gemm<64, 1, 1, 1, 2>, cudaFuncAttributeMaxDynamicSharedMemorySize, sm64);
    cudaFuncSetAttribute(k_gemm<64, 1, 0, 0, 0>, cudaFuncAttributeMaxDynamicSharedMemorySize, sm64);

    // ---- CSR build
    k_zero_cnt<<<NROWS / 256, 256>>>();
    k_hist<<<(E + 255) / 256, 256>>>(dst, E);
    k_scan1<<<256, 128>>>();
    k_scan2<<<1, 256>>>();
    k_scan3<<<NROWS / 256, 256>>>(E);
    k_place<<<(E + 255) / 256, 256>>>(src, dst, E);

    // ---- layer 1
    k_gather32<<<NROWS / 8, 256>>>(x, bufA);
    k_gemm<32, 1, 0, 0, 0><<<1024, 256, sm32>>>(bufA, gcn1_w, gcn1_b, bufB);
    k_gemm<64, 3, 0, 2, 1><<<1024, 256, sm64t>>>(bufB, t1_w, t1_b, bufC);
    k_bn_fin<<<1, 64>>>(bn1_g, bn1_b);
    k_gemm<64, 1, 1, 1, 2><<<1024, 256, sm64>>>(bufC, o1_w, o1_b, bufA);

    // ---- layer 2
    k_gather64<<<NROWS / 8, 256>>>(bufA, bufB);
    k_gemm<64, 1, 0, 0, 0><<<1024, 256, sm64>>>(bufB, gcn2_w, gcn2_b, bufC);
    k_gemm<64, 3, 0, 2, 1><<<1024, 256, sm64t>>>(bufC, t2_w, t2_b, bufB);
    k_bn_fin<<<1, 64>>>(bn2_g, bn2_b);
    k_gemm<64, 1, 1, 1, 2><<<1024, 256, sm64>>>(bufB, o2_w, o2_b, bufC);

    // ---- regression + mean
    k_prep_reg<<<4, 256>>>(reg_w, reg_b, out);
    k_reg<<<NROWS / 256, 256>>>(bufC, out);
}